// round 15
// baseline (speedup 1.0000x reference)
#include <cuda_runtime.h>
#include <cuda_bf16.h>
#include <math.h>
#include <stdint.h>

// Problem constants
#define Bq 2
#define Sq 2048
#define Dm 1024
#define Hn 16
#define DP 64
#define BH (Bq * Hn)       // 32
#define Mrows (Bq * Sq)    // 4096

// Scratch (device globals: no allocation allowed)
__device__ __nv_bfloat16 g_qhh[BH * Sq * DP], g_qhl[BH * Sq * DP];
__device__ __nv_bfloat16 g_khh[BH * Sq * DP], g_khl[BH * Sq * DP];
__device__ __nv_bfloat16 g_vhh[BH * Sq * DP], g_vhl[BH * Sq * DP];
__device__ float g_attn[Mrows * Dm];
__device__ float g_rowsum[BH * Sq];

__device__ __forceinline__ uint32_t smem_u32(const void* p) {
    uint32_t a;
    asm("{ .reg .u64 t; cvta.to.shared.u64 t, %1; cvt.u32.u64 %0, t; }"
        : "=r"(a) : "l"(p));
    return a;
}
__device__ __forceinline__ void ldmat4(uint32_t* f, uint32_t addr) {
    asm volatile("ldmatrix.sync.aligned.m8n8.x4.shared.b16 {%0,%1,%2,%3}, [%4];"
                 : "=r"(f[0]), "=r"(f[1]), "=r"(f[2]), "=r"(f[3]) : "r"(addr));
}
__device__ __forceinline__ void ldmat4t(uint32_t* f, uint32_t addr) {
    asm volatile("ldmatrix.sync.aligned.m8n8.x4.trans.shared.b16 {%0,%1,%2,%3}, [%4];"
                 : "=r"(f[0]), "=r"(f[1]), "=r"(f[2]), "=r"(f[3]) : "r"(addr));
}
__device__ __forceinline__ void mma16816(float* d, const uint32_t* a,
                                         uint32_t b0, uint32_t b1) {
    asm volatile(
        "mma.sync.aligned.m16n8k16.row.col.f32.bf16.bf16.f32 "
        "{%0,%1,%2,%3}, {%4,%5,%6,%7}, {%8,%9}, {%0,%1,%2,%3};"
        : "+f"(d[0]), "+f"(d[1]), "+f"(d[2]), "+f"(d[3])
        : "r"(a[0]), "r"(a[1]), "r"(a[2]), "r"(a[3]), "r"(b0), "r"(b1));
}
__device__ __forceinline__ uint32_t pack2bf16(float x, float y) {
    __nv_bfloat162 h = __floats2bfloat162_rn(x, y);
    return *(uint32_t*)&h;
}
__device__ __forceinline__ float bf16hi(float x) {
    return __bfloat162float(__float2bfloat16_rn(x));
}
__device__ __forceinline__ void cp16(uint32_t dst, const void* src) {
    asm volatile("cp.async.cg.shared.global [%0], [%1], 16;"
                 :: "r"(dst), "l"(src));
}
#define CP_COMMIT() asm volatile("cp.async.commit_group;" ::: "memory")
#define CP_WAIT0()  asm volatile("cp.async.wait_group 0;" ::: "memory")

// ===========================================================================
// mma.sync bf16-split GEMM (R14 plane-pass version, unchanged)
// ===========================================================================
#define LDB 40

__global__ __launch_bounds__(256, 2) void tc_gemm(
    const float* __restrict__ A, const float* __restrict__ W,
    const float* __restrict__ bias, float* __restrict__ C,
    __nv_bfloat16* __restrict__ CH, __nv_bfloat16* __restrict__ CL,
    int headSplit)
{
    __shared__ __nv_bfloat16 AH[128 * LDB];
    __shared__ __nv_bfloat16 AL[128 * LDB];
    __shared__ __nv_bfloat16 WH[128 * LDB];
    __shared__ __nv_bfloat16 WL[128 * LDB];

    const int tid = threadIdx.x;
    const int wid = tid >> 5, lane = tid & 31;
    const int wm = wid & 3, wn = wid >> 2;
    const int m0 = blockIdx.y * 128, n0 = blockIdx.x * 128;

    const uint32_t sAH = smem_u32(AH), sAL = smem_u32(AL);
    const uint32_t sWH = smem_u32(WH), sWL = smem_u32(WL);

    const int lr = tid >> 1;
    const int lko = (tid & 1) * 16;
    const float* aptr = A + (size_t)(m0 + lr) * Dm + lko;
    const float* wptr = W + (size_t)(n0 + lr) * Dm + lko;
    __nv_bfloat16* pAH = AH + lr * LDB + lko;
    __nv_bfloat16* pAL = AL + lr * LDB + lko;
    __nv_bfloat16* pWH = WH + lr * LDB + lko;
    __nv_bfloat16* pWL = WL + lr * LDB + lko;

    float acc[2][8][4];
#pragma unroll
    for (int i = 0; i < 2; i++)
#pragma unroll
        for (int j = 0; j < 8; j++)
#pragma unroll
            for (int x = 0; x < 4; x++) acc[i][j][x] = 0.0f;

    const int lrow = lane & 15;
    const int lcol = (lane >> 4) << 3;

    for (int t = 0; t < 32; t++) {
        const int kt = t * 32;
        {
            float v[16];
#pragma unroll
            for (int q4 = 0; q4 < 4; q4++)
                *(float4*)&v[q4 * 4] = *(const float4*)&aptr[kt + q4 * 4];
            uint32_t hi[8], lo[8];
#pragma unroll
            for (int e = 0; e < 8; e++) {
                float h0 = bf16hi(v[2 * e]), h1 = bf16hi(v[2 * e + 1]);
                hi[e] = pack2bf16(v[2 * e], v[2 * e + 1]);
                lo[e] = pack2bf16(v[2 * e] - h0, v[2 * e + 1] - h1);
            }
            *(uint4*)pAH = make_uint4(hi[0], hi[1], hi[2], hi[3]);
            *(uint4*)(pAH + 8) = make_uint4(hi[4], hi[5], hi[6], hi[7]);
            *(uint4*)pAL = make_uint4(lo[0], lo[1], lo[2], lo[3]);
            *(uint4*)(pAL + 8) = make_uint4(lo[4], lo[5], lo[6], lo[7]);

#pragma unroll
            for (int q4 = 0; q4 < 4; q4++)
                *(float4*)&v[q4 * 4] = *(const float4*)&wptr[kt + q4 * 4];
#pragma unroll
            for (int e = 0; e < 8; e++) {
                float h0 = bf16hi(v[2 * e]), h1 = bf16hi(v[2 * e + 1]);
                hi[e] = pack2bf16(v[2 * e], v[2 * e + 1]);
                lo[e] = pack2bf16(v[2 * e] - h0, v[2 * e + 1] - h1);
            }
            *(uint4*)pWH = make_uint4(hi[0], hi[1], hi[2], hi[3]);
            *(uint4*)(pWH + 8) = make_uint4(hi[4], hi[5], hi[6], hi[7]);
            *(uint4*)pWL = make_uint4(lo[0], lo[1], lo[2], lo[3]);
            *(uint4*)(pWL + 8) = make_uint4(lo[4], lo[5], lo[6], lo[7]);
        }
        __syncthreads();

#pragma unroll
        for (int kk = 0; kk < 32; kk += 16) {
            uint32_t ah[2][4], al[2][4];
#pragma unroll
            for (int mt = 0; mt < 2; mt++) {
                uint32_t off = (uint32_t)((wm * 32 + mt * 16 + lrow) * LDB + kk + lcol) * 2;
                ldmat4(ah[mt], sAH + off);
                ldmat4(al[mt], sAL + off);
            }
            uint32_t wh4[4][4], wl4[4][4];
#pragma unroll
            for (int nt4 = 0; nt4 < 4; nt4++) {
                uint32_t off = (uint32_t)((wn * 64 + nt4 * 16 + lrow) * LDB + kk + lcol) * 2;
                ldmat4(wh4[nt4], sWH + off);
                ldmat4(wl4[nt4], sWL + off);
            }
#pragma unroll
            for (int nt4 = 0; nt4 < 4; nt4++)
#pragma unroll
                for (int mt = 0; mt < 2; mt++) {
                    mma16816(acc[mt][2 * nt4],     ah[mt], wh4[nt4][0], wh4[nt4][2]);
                    mma16816(acc[mt][2 * nt4 + 1], ah[mt], wh4[nt4][1], wh4[nt4][3]);
                }
#pragma unroll
            for (int nt4 = 0; nt4 < 4; nt4++)
#pragma unroll
                for (int mt = 0; mt < 2; mt++) {
                    mma16816(acc[mt][2 * nt4],     ah[mt], wl4[nt4][0], wl4[nt4][2]);
                    mma16816(acc[mt][2 * nt4 + 1], ah[mt], wl4[nt4][1], wl4[nt4][3]);
                }
#pragma unroll
            for (int nt4 = 0; nt4 < 4; nt4++)
#pragma unroll
                for (int mt = 0; mt < 2; mt++) {
                    mma16816(acc[mt][2 * nt4],     al[mt], wh4[nt4][0], wh4[nt4][2]);
                    mma16816(acc[mt][2 * nt4 + 1], al[mt], wh4[nt4][1], wh4[nt4][3]);
                }
        }
        __syncthreads();
    }

    const int lrq = lane >> 2;
    const int lc2 = (lane & 3) * 2;
#pragma unroll
    for (int mt = 0; mt < 2; mt++) {
#pragma unroll
        for (int nt = 0; nt < 8; nt++) {
            int col = n0 + wn * 64 + nt * 8 + lc2;
            float b0 = bias[col], b1 = bias[col + 1];
#pragma unroll
            for (int half = 0; half < 2; half++) {
                int row = m0 + wm * 32 + mt * 16 + lrq + half * 8;
                float ox = acc[mt][nt][half * 2 + 0] + b0;
                float oy = acc[mt][nt][half * 2 + 1] + b1;
                if (!headSplit) {
                    *(float2*)&C[(size_t)row * Dm + col] = make_float2(ox, oy);
                } else {
                    int bb = row >> 11, sI = row & 2047;
                    int h = col >> 6, dd = col & 63;
                    size_t base = ((size_t)(bb * Hn + h) * Sq + sI) * DP + dd;
                    float h0 = bf16hi(ox), h1 = bf16hi(oy);
                    *(uint32_t*)&CH[base] = pack2bf16(ox, oy);
                    *(uint32_t*)&CL[base] = pack2bf16(ox - h0, oy - h1);
                }
            }
        }
    }
}

// ===========================================================================
// attn_tc: 512 threads, 16 warps = 8 m-groups x 2 k-halves.
// Tile 128q x 128k; each warp: QK over its 64-k half, epilogue for its
// 16q x 64k block, AV partial over its k-half. smem exchange merges halves.
// ===========================================================================
#define KLD 72
#define OQH 0
#define OQL (128 * KLD * 2)
#define OKV0 (2 * 128 * KLD * 2)        // 36864
#define KVBUF (4 * 128 * KLD * 2)       // 73728
#define SKH 0
#define SKL (128 * KLD * 2)
#define SVH (2 * 128 * KLD * 2)
#define SVL (3 * 128 * KLD * 2)
#define ORS (OKV0 + 2 * KVBUF)          // 184320 (2*128 floats)
#define OINV (ORS + 1024)               // 128 floats
#define ASMEM (OINV + 512)              // 185344
#define OAX OKV0                        // accA exchange reuses KV space (32KB)

__global__ __launch_bounds__(512, 1) void attn_tc(
    const float* __restrict__ mask, float* __restrict__ wout)
{
    extern __shared__ char smb[];
    const uint32_t sb = smem_u32(smb);
    float* RS  = (float*)(smb + ORS);
    float* INV = (float*)(smb + OINV);
    float* AX  = (float*)(smb + OAX);

    const int tid = threadIdx.x;
    const int wid = tid >> 5, lane = tid & 31;
    const int wm = wid & 7;            // q-row group (16 rows)
    const int wk = wid >> 3;           // k-half (0/1)
    const int qb = blockIdx.x;
    const int bh = blockIdx.y;
    const int b = bh >> 4, h = bh & 15;

    const int lrow = lane & 15;
    const int lcol = (lane >> 4) << 3;
    const int lrq = lane >> 2;
    const int lc2 = (lane & 3) * 2;

    const __nv_bfloat16* qHg = g_qhh + ((size_t)bh * Sq + qb * 128) * DP;
    const __nv_bfloat16* qLg = g_qhl + ((size_t)bh * Sq + qb * 128) * DP;
    const __nv_bfloat16* kHg = g_khh + (size_t)bh * Sq * DP;
    const __nv_bfloat16* kLg = g_khl + (size_t)bh * Sq * DP;
    const __nv_bfloat16* vHg = g_vhh + (size_t)bh * Sq * DP;
    const __nv_bfloat16* vLg = g_vhl + (size_t)bh * Sq * DP;

    // loader: 4 threads per row, each 32B (2 cp16) per plane
    const int ldr = tid >> 2;            // 0..127
    const int ldc = (tid & 3) * 16;      // bf16 col 0/16/32/48
    const uint32_t dro = (uint32_t)(ldr * KLD + ldc) * 2;
    const size_t sro = (size_t)ldr * DP + ldc;

#pragma unroll
    for (int c = 0; c < 2; c++) {
        cp16(sb + OQH + dro + c * 16, qHg + sro + c * 8);
        cp16(sb + OQL + dro + c * 16, qLg + sro + c * 8);
        cp16(sb + OKV0 + SKH + dro + c * 16, kHg + sro + c * 8);
        cp16(sb + OKV0 + SKL + dro + c * 16, kLg + sro + c * 8);
        cp16(sb + OKV0 + SVH + dro + c * 16, vHg + sro + c * 8);
        cp16(sb + OKV0 + SVL + dro + c * 16, vLg + sro + c * 8);
    }
    CP_COMMIT();

    float accA[8][4];
#pragma unroll
    for (int j = 0; j < 8; j++)
#pragma unroll
        for (int x = 0; x < 4; x++) accA[j][x] = 0.0f;
    float rsum[2] = {0.f, 0.f};

    const int qrow0 = wm * 16;
    const int kc0 = wk * 64;     // this warp's k-column base within tile

    for (int kt = 0; kt < 16; kt++) {
        CP_WAIT0();
        __syncthreads();

        const uint32_t kvo = sb + OKV0 + (kt & 1) * KVBUF;
        const int ktbase = kt * 128;

        if (kt < 15) {
            const uint32_t nxt = sb + OKV0 + ((kt + 1) & 1) * KVBUF;
            const size_t gi = (size_t)(kt + 1) * 128 * DP + sro;
#pragma unroll
            for (int c = 0; c < 2; c++) {
                cp16(nxt + SKH + dro + c * 16, kHg + gi + c * 8);
                cp16(nxt + SKL + dro + c * 16, kLg + gi + c * 8);
                cp16(nxt + SVH + dro + c * 16, vHg + gi + c * 8);
                cp16(nxt + SVL + dro + c * 16, vLg + gi + c * 8);
            }
            CP_COMMIT();
        }

        // ---- QK^T over this warp's 64-k half ----
        float s[8][4];
#pragma unroll
        for (int j = 0; j < 8; j++)
#pragma unroll
            for (int x = 0; x < 4; x++) s[j][x] = 0.0f;

#pragma unroll
        for (int kk = 0; kk < 64; kk += 16) {
            uint32_t ah[4], al[4];
            uint32_t qoff = (uint32_t)((qrow0 + lrow) * KLD + kk + lcol) * 2;
            ldmat4(ah, sb + OQH + qoff);
            ldmat4(al, sb + OQL + qoff);
#pragma unroll
            for (int nt4 = 0; nt4 < 4; nt4++) {
                uint32_t koff = (uint32_t)((kc0 + nt4 * 16 + lrow) * KLD + kk + lcol) * 2;
                uint32_t bh4[4], bl4[4];
                ldmat4(bh4, kvo + SKH + koff);
                ldmat4(bl4, kvo + SKL + koff);
                mma16816(s[2 * nt4],     ah, bh4[0], bh4[2]);
                mma16816(s[2 * nt4 + 1], ah, bh4[1], bh4[3]);
                mma16816(s[2 * nt4],     ah, bl4[0], bl4[2]);
                mma16816(s[2 * nt4 + 1], ah, bl4[1], bl4[3]);
                mma16816(s[2 * nt4],     al, bh4[0], bh4[2]);
                mma16816(s[2 * nt4 + 1], al, bh4[1], bh4[3]);
            }
        }

        // ---- epilogue for this warp's 16q x 64k block ----
        uint32_t eh[4][4], el[4][4];
#pragma unroll
        for (int j = 0; j < 8; j++) {
#pragma unroll
            for (int half = 0; half < 2; half++) {
                int ql = qrow0 + lrq + half * 8;
                size_t qg = (size_t)qb * 128 + ql;
                size_t gk = (size_t)ktbase + kc0 + j * 8 + lc2;
                float2 mv = *(const float2*)&mask[((size_t)b * Sq + qg) * Sq + gk];
                float e0 = __expf(s[j][half * 2 + 0] * 0.125f + mv.x * (-1e9f));
                float e1 = __expf(s[j][half * 2 + 1] * 0.125f + mv.y * (-1e9f));
                *(float2*)&wout[((size_t)bh * Sq + qg) * Sq + gk] = make_float2(e0, e1);
                float h0 = bf16hi(e0), h1 = bf16hi(e1);
                eh[j >> 1][(j & 1) * 2 + half] = pack2bf16(e0, e1);
                el[j >> 1][(j & 1) * 2 + half] = pack2bf16(e0 - h0, e1 - h1);
                rsum[half] += e0 + e1;
            }
        }

        // ---- AV partial over this warp's k-half ----
#pragma unroll
        for (int kk4 = 0; kk4 < 4; kk4++) {
#pragma unroll
            for (int dt4 = 0; dt4 < 4; dt4++) {
                uint32_t voff = (uint32_t)((kc0 + kk4 * 16 + lrow) * KLD + dt4 * 16 + lcol) * 2;
                uint32_t vh4[4], vl4[4];
                ldmat4t(vh4, kvo + SVH + voff);
                ldmat4t(vl4, kvo + SVL + voff);
                mma16816(accA[dt4 * 2],     eh[kk4], vh4[0], vh4[1]);
                mma16816(accA[dt4 * 2 + 1], eh[kk4], vh4[2], vh4[3]);
                mma16816(accA[dt4 * 2],     eh[kk4], vl4[0], vl4[1]);
                mma16816(accA[dt4 * 2 + 1], eh[kk4], vl4[2], vl4[3]);
                mma16816(accA[dt4 * 2],     el[kk4], vh4[0], vh4[1]);
                mma16816(accA[dt4 * 2 + 1], el[kk4], vh4[2], vh4[3]);
            }
        }
    }

    // ---- rowsum: quad-reduce, store per-k-half ----
#pragma unroll
    for (int half = 0; half < 2; half++) {
        float r = rsum[half];
        r += __shfl_xor_sync(0xFFFFFFFFu, r, 1);
        r += __shfl_xor_sync(0xFFFFFFFFu, r, 2);
        if ((lane & 3) == 0) RS[wk * 128 + qrow0 + lrq + half * 8] = r;
    }

    // ---- wk=0 warps stage their AV partial in smem (KV space is dead) ----
    if (wk == 0) {
#pragma unroll
        for (int nt = 0; nt < 8; nt++)
#pragma unroll
            for (int half = 0; half < 2; half++) {
                int ql = qrow0 + lrq + half * 8;
                *(float2*)&AX[ql * 64 + nt * 8 + lc2] =
                    make_float2(accA[nt][half * 2], accA[nt][half * 2 + 1]);
            }
    }
    __syncthreads();

    if (tid < 128) {
        float tot = RS[tid] + RS[128 + tid];
        g_rowsum[(size_t)bh * Sq + qb * 128 + tid] = tot;
        INV[tid] = 1.0f / tot;
    }
    __syncthreads();

    // ---- wk=1 warps merge halves, normalize, store ----
    if (wk == 1) {
#pragma unroll
        for (int nt = 0; nt < 8; nt++) {
            int dcol = nt * 8 + lc2;
#pragma unroll
            for (int half = 0; half < 2; half++) {
                int ql = qrow0 + lrq + half * 8;
                float inv = INV[ql];
                size_t qg = (size_t)qb * 128 + ql;
                float2 p = *(float2*)&AX[ql * 64 + dcol];
                float2 o = make_float2((accA[nt][half * 2] + p.x) * inv,
                                       (accA[nt][half * 2 + 1] + p.y) * inv);
                *(float2*)&g_attn[((size_t)b * Sq + qg) * Dm + h * 64 + dcol] = o;
            }
        }
    }
}

// ---------------------------------------------------------------------------
__global__ __launch_bounds__(128) void norm_kernel(float* __restrict__ w)
{
    int row = blockIdx.x;
    float inv = 1.0f / g_rowsum[row];
    float4* p = (float4*)(w + (size_t)row * Sq);
#pragma unroll
    for (int t = threadIdx.x; t < Sq / 4; t += 128) {
        float4 v = p[t];
        v.x *= inv; v.y *= inv; v.z *= inv; v.w *= inv;
        p[t] = v;
    }
}

// ---------------------------------------------------------------------------
extern "C" void kernel_launch(void* const* d_in, const int* in_sizes, int n_in,
                              void* d_out, int out_size)
{
    const float* q    = (const float*)d_in[0];
    const float* v    = (const float*)d_in[1];
    const float* k    = (const float*)d_in[2];
    const float* mask = (const float*)d_in[3];
    const float* wq_w = (const float*)d_in[4];
    const float* wq_b = (const float*)d_in[5];
    const float* wk_w = (const float*)d_in[6];
    const float* wk_b = (const float*)d_in[7];
    const float* wv_w = (const float*)d_in[8];
    const float* wv_b = (const float*)d_in[9];
    const float* dw   = (const float*)d_in[10];
    const float* db   = (const float*)d_in[11];

    float* out     = (float*)d_out;
    float* weights = out + (size_t)Mrows * Dm;

    __nv_bfloat16 *qhh, *qhl, *khh, *khl, *vhh, *vhl;
    float* attn;
    cudaGetSymbolAddress((void**)&qhh, g_qhh);
    cudaGetSymbolAddress((void**)&qhl, g_qhl);
    cudaGetSymbolAddress((void**)&khh, g_khh);
    cudaGetSymbolAddress((void**)&khl, g_khl);
    cudaGetSymbolAddress((void**)&vhh, g_vhh);
    cudaGetSymbolAddress((void**)&vhl, g_vhl);
    cudaGetSymbolAddress((void**)&attn, g_attn);

    dim3 g(Dm / 128, Mrows / 128);   // (8, 32)

    cudaFuncSetAttribute(attn_tc, cudaFuncAttributeMaxDynamicSharedMemorySize, ASMEM);

    // fork-join streams: run K/V projections and norm||dense concurrently
    cudaStream_t s2, s3;
    cudaStreamCreateWithFlags(&s2, cudaStreamNonBlocking);
    cudaStreamCreateWithFlags(&s3, cudaStreamNonBlocking);
    cudaEvent_t e0, ek, ev, e1, e2;
    cudaEventCreateWithFlags(&e0, cudaEventDisableTiming);
    cudaEventCreateWithFlags(&ek, cudaEventDisableTiming);
    cudaEventCreateWithFlags(&ev, cudaEventDisableTiming);
    cudaEventCreateWithFlags(&e1, cudaEventDisableTiming);
    cudaEventCreateWithFlags(&e2, cudaEventDisableTiming);

    cudaEventRecord(e0, 0);
    cudaStreamWaitEvent(s2, e0, 0);
    cudaStreamWaitEvent(s3, e0, 0);

    tc_gemm<<<g, 256, 0, 0>>>(q, wq_w, wq_b, nullptr, qhh, qhl, 1);
    tc_gemm<<<g, 256, 0, s2>>>(k, wk_w, wk_b, nullptr, khh, khl, 1);
    tc_gemm<<<g, 256, 0, s3>>>(v, wv_w, wv_b, nullptr, vhh, vhl, 1);

    cudaEventRecord(ek, s2);
    cudaEventRecord(ev, s3);
    cudaStreamWaitEvent(0, ek, 0);
    cudaStreamWaitEvent(0, ev, 0);

    attn_tc<<<dim3(Sq / 128, BH), 512, ASMEM, 0>>>(mask, weights);

    cudaEventRecord(e1, 0);
    cudaStreamWaitEvent(s2, e1, 0);
    norm_kernel<<<BH * Sq, 128, 0, s2>>>(weights);
    cudaEventRecord(e2, s2);

    tc_gemm<<<g, 256, 0, 0>>>(attn, dw, db, out, nullptr, nullptr, 0);

    cudaStreamWaitEvent(0, e2, 0);

    cudaEventDestroy(e0);
    cudaEventDestroy(ek);
    cudaEventDestroy(ev);
    cudaEventDestroy(e1);
    cudaEventDestroy(e2);
    cudaStreamDestroy(s2);
    cudaStreamDestroy(s3);
}

// round 17
// speedup vs baseline: 1.1751x; 1.1751x over previous
#include <cuda_runtime.h>
#include <cuda_bf16.h>
#include <cuda_fp16.h>
#include <math.h>
#include <stdint.h>

// Problem constants
#define Bq 2
#define Sq 2048
#define Dm 1024
#define Hn 16
#define DP 64
#define BH (Bq * Hn)       // 32
#define Mrows (Bq * Sq)    // 4096

// Scratch (device globals: no allocation allowed)
__device__ __half g_qhh[BH * Sq * DP], g_qhl[BH * Sq * DP];
__device__ __half g_khh[BH * Sq * DP], g_khl[BH * Sq * DP];
__device__ __half g_vhh[BH * Sq * DP], g_vhl[BH * Sq * DP];
__device__ float g_attn[Mrows * Dm];
__device__ float g_rowsum[BH * Sq];

__device__ __forceinline__ uint32_t smem_u32(const void* p) {
    uint32_t a;
    asm("{ .reg .u64 t; cvta.to.shared.u64 t, %1; cvt.u32.u64 %0, t; }"
        : "=r"(a) : "l"(p));
    return a;
}
__device__ __forceinline__ void ldmat4(uint32_t* f, uint32_t addr) {
    asm volatile("ldmatrix.sync.aligned.m8n8.x4.shared.b16 {%0,%1,%2,%3}, [%4];"
                 : "=r"(f[0]), "=r"(f[1]), "=r"(f[2]), "=r"(f[3]) : "r"(addr));
}
__device__ __forceinline__ void ldmat4t(uint32_t* f, uint32_t addr) {
    asm volatile("ldmatrix.sync.aligned.m8n8.x4.trans.shared.b16 {%0,%1,%2,%3}, [%4];"
                 : "=r"(f[0]), "=r"(f[1]), "=r"(f[2]), "=r"(f[3]) : "r"(addr));
}
// bf16 mma (GEMMs)
__device__ __forceinline__ void mma16816(float* d, const uint32_t* a,
                                         uint32_t b0, uint32_t b1) {
    asm volatile(
        "mma.sync.aligned.m16n8k16.row.col.f32.bf16.bf16.f32 "
        "{%0,%1,%2,%3}, {%4,%5,%6,%7}, {%8,%9}, {%0,%1,%2,%3};"
        : "+f"(d[0]), "+f"(d[1]), "+f"(d[2]), "+f"(d[3])
        : "r"(a[0]), "r"(a[1]), "r"(a[2]), "r"(a[3]), "r"(b0), "r"(b1));
}
// fp16 mma (attention)
__device__ __forceinline__ void mma16816h(float* d, const uint32_t* a,
                                          uint32_t b0, uint32_t b1) {
    asm volatile(
        "mma.sync.aligned.m16n8k16.row.col.f32.f16.f16.f32 "
        "{%0,%1,%2,%3}, {%4,%5,%6,%7}, {%8,%9}, {%0,%1,%2,%3};"
        : "+f"(d[0]), "+f"(d[1]), "+f"(d[2]), "+f"(d[3])
        : "r"(a[0]), "r"(a[1]), "r"(a[2]), "r"(a[3]), "r"(b0), "r"(b1));
}
__device__ __forceinline__ uint32_t pack2bf16(float x, float y) {
    __nv_bfloat162 h = __floats2bfloat162_rn(x, y);
    return *(uint32_t*)&h;
}
__device__ __forceinline__ float bf16hi(float x) {
    return __bfloat162float(__float2bfloat16_rn(x));
}
__device__ __forceinline__ uint32_t pack2half(float x, float y) {
    __half2 h = __floats2half2_rn(x, y);
    return *(uint32_t*)&h;
}
__device__ __forceinline__ float halfhi(float x) {
    return __half2float(__float2half_rn(x));
}
__device__ __forceinline__ void cp16(uint32_t dst, const void* src) {
    asm volatile("cp.async.cg.shared.global [%0], [%1], 16;"
                 :: "r"(dst), "l"(src));
}
#define CP_COMMIT() asm volatile("cp.async.commit_group;" ::: "memory")
#define CP_WAIT0()  asm volatile("cp.async.wait_group 0;" ::: "memory")

// ===========================================================================
// mma.sync bf16-split GEMM (plane-pass). headSplit=1: emit fp16 hi/lo planes.
// ===========================================================================
#define LDB 40

__global__ __launch_bounds__(256, 2) void tc_gemm(
    const float* __restrict__ A, const float* __restrict__ W,
    const float* __restrict__ bias, float* __restrict__ C,
    __half* __restrict__ CH, __half* __restrict__ CL,
    int headSplit)
{
    __shared__ __nv_bfloat16 AH[128 * LDB];
    __shared__ __nv_bfloat16 AL[128 * LDB];
    __shared__ __nv_bfloat16 WH[128 * LDB];
    __shared__ __nv_bfloat16 WL[128 * LDB];

    const int tid = threadIdx.x;
    const int wid = tid >> 5, lane = tid & 31;
    const int wm = wid & 3, wn = wid >> 2;
    const int m0 = blockIdx.y * 128, n0 = blockIdx.x * 128;

    const uint32_t sAH = smem_u32(AH), sAL = smem_u32(AL);
    const uint32_t sWH = smem_u32(WH), sWL = smem_u32(WL);

    const int lr = tid >> 1;
    const int lko = (tid & 1) * 16;
    const float* aptr = A + (size_t)(m0 + lr) * Dm + lko;
    const float* wptr = W + (size_t)(n0 + lr) * Dm + lko;
    __nv_bfloat16* pAH = AH + lr * LDB + lko;
    __nv_bfloat16* pAL = AL + lr * LDB + lko;
    __nv_bfloat16* pWH = WH + lr * LDB + lko;
    __nv_bfloat16* pWL = WL + lr * LDB + lko;

    float acc[2][8][4];
#pragma unroll
    for (int i = 0; i < 2; i++)
#pragma unroll
        for (int j = 0; j < 8; j++)
#pragma unroll
            for (int x = 0; x < 4; x++) acc[i][j][x] = 0.0f;

    const int lrow = lane & 15;
    const int lcol = (lane >> 4) << 3;

    for (int t = 0; t < 32; t++) {
        const int kt = t * 32;
        {
            float v[16];
#pragma unroll
            for (int q4 = 0; q4 < 4; q4++)
                *(float4*)&v[q4 * 4] = *(const float4*)&aptr[kt + q4 * 4];
            uint32_t hi[8], lo[8];
#pragma unroll
            for (int e = 0; e < 8; e++) {
                float h0 = bf16hi(v[2 * e]), h1 = bf16hi(v[2 * e + 1]);
                hi[e] = pack2bf16(v[2 * e], v[2 * e + 1]);
                lo[e] = pack2bf16(v[2 * e] - h0, v[2 * e + 1] - h1);
            }
            *(uint4*)pAH = make_uint4(hi[0], hi[1], hi[2], hi[3]);
            *(uint4*)(pAH + 8) = make_uint4(hi[4], hi[5], hi[6], hi[7]);
            *(uint4*)pAL = make_uint4(lo[0], lo[1], lo[2], lo[3]);
            *(uint4*)(pAL + 8) = make_uint4(lo[4], lo[5], lo[6], lo[7]);

#pragma unroll
            for (int q4 = 0; q4 < 4; q4++)
                *(float4*)&v[q4 * 4] = *(const float4*)&wptr[kt + q4 * 4];
#pragma unroll
            for (int e = 0; e < 8; e++) {
                float h0 = bf16hi(v[2 * e]), h1 = bf16hi(v[2 * e + 1]);
                hi[e] = pack2bf16(v[2 * e], v[2 * e + 1]);
                lo[e] = pack2bf16(v[2 * e] - h0, v[2 * e + 1] - h1);
            }
            *(uint4*)pWH = make_uint4(hi[0], hi[1], hi[2], hi[3]);
            *(uint4*)(pWH + 8) = make_uint4(hi[4], hi[5], hi[6], hi[7]);
            *(uint4*)pWL = make_uint4(lo[0], lo[1], lo[2], lo[3]);
            *(uint4*)(pWL + 8) = make_uint4(lo[4], lo[5], lo[6], lo[7]);
        }
        __syncthreads();

#pragma unroll
        for (int kk = 0; kk < 32; kk += 16) {
            uint32_t ah[2][4], al[2][4];
#pragma unroll
            for (int mt = 0; mt < 2; mt++) {
                uint32_t off = (uint32_t)((wm * 32 + mt * 16 + lrow) * LDB + kk + lcol) * 2;
                ldmat4(ah[mt], sAH + off);
                ldmat4(al[mt], sAL + off);
            }
            uint32_t wh4[4][4], wl4[4][4];
#pragma unroll
            for (int nt4 = 0; nt4 < 4; nt4++) {
                uint32_t off = (uint32_t)((wn * 64 + nt4 * 16 + lrow) * LDB + kk + lcol) * 2;
                ldmat4(wh4[nt4], sWH + off);
                ldmat4(wl4[nt4], sWL + off);
            }
#pragma unroll
            for (int nt4 = 0; nt4 < 4; nt4++)
#pragma unroll
                for (int mt = 0; mt < 2; mt++) {
                    mma16816(acc[mt][2 * nt4],     ah[mt], wh4[nt4][0], wh4[nt4][2]);
                    mma16816(acc[mt][2 * nt4 + 1], ah[mt], wh4[nt4][1], wh4[nt4][3]);
                }
#pragma unroll
            for (int nt4 = 0; nt4 < 4; nt4++)
#pragma unroll
                for (int mt = 0; mt < 2; mt++) {
                    mma16816(acc[mt][2 * nt4],     ah[mt], wl4[nt4][0], wl4[nt4][2]);
                    mma16816(acc[mt][2 * nt4 + 1], ah[mt], wl4[nt4][1], wl4[nt4][3]);
                }
#pragma unroll
            for (int nt4 = 0; nt4 < 4; nt4++)
#pragma unroll
                for (int mt = 0; mt < 2; mt++) {
                    mma16816(acc[mt][2 * nt4],     al[mt], wh4[nt4][0], wh4[nt4][2]);
                    mma16816(acc[mt][2 * nt4 + 1], al[mt], wh4[nt4][1], wh4[nt4][3]);
                }
        }
        __syncthreads();
    }

    const int lrq = lane >> 2;
    const int lc2 = (lane & 3) * 2;
#pragma unroll
    for (int mt = 0; mt < 2; mt++) {
#pragma unroll
        for (int nt = 0; nt < 8; nt++) {
            int col = n0 + wn * 64 + nt * 8 + lc2;
            float b0 = bias[col], b1 = bias[col + 1];
#pragma unroll
            for (int half = 0; half < 2; half++) {
                int row = m0 + wm * 32 + mt * 16 + lrq + half * 8;
                float ox = acc[mt][nt][half * 2 + 0] + b0;
                float oy = acc[mt][nt][half * 2 + 1] + b1;
                if (!headSplit) {
                    *(float2*)&C[(size_t)row * Dm + col] = make_float2(ox, oy);
                } else {
                    int bb = row >> 11, sI = row & 2047;
                    int h = col >> 6, dd = col & 63;
                    size_t base = ((size_t)(bb * Hn + h) * Sq + sI) * DP + dd;
                    float h0 = halfhi(ox), h1 = halfhi(oy);
                    *(uint32_t*)&CH[base] = pack2half(ox, oy);
                    *(uint32_t*)&CL[base] = pack2half(ox - h0, oy - h1);
                }
            }
        }
    }
}

// ===========================================================================
// attn_tc (fp16): 256 threads, 8 warps x 16 q-rows, k-tiles of 128.
// QK = qh*(kh+kl)  [2 planes]; AV = Eh*Vh [1 plane]. Double-buffered KV.
// ===========================================================================
#define KLD 72
#define OQH 0
#define OKV0 (128 * KLD * 2)             // 18432
#define KVBUF (3 * 128 * KLD * 2)        // 55296 (KH, KL, VH)
#define SKH 0
#define SKL (128 * KLD * 2)
#define SVH (2 * 128 * KLD * 2)
#define ORS (OKV0 + 2 * KVBUF)           // 129024
#define ASMEM (ORS + 128 * 4)            // 129536

__global__ __launch_bounds__(256, 1) void attn_tc(
    const float* __restrict__ mask, float* __restrict__ wout)
{
    extern __shared__ char smb[];
    const uint32_t sb = smem_u32(smb);
    float* RS = (float*)(smb + ORS);

    const int tid = threadIdx.x;
    const int wid = tid >> 5, lane = tid & 31;
    const int qb = blockIdx.x;
    const int bh = blockIdx.y;
    const int b = bh >> 4, h = bh & 15;

    const int lrow = lane & 15;
    const int lcol = (lane >> 4) << 3;
    const int lrq = lane >> 2;
    const int lc2 = (lane & 3) * 2;

    const __half* qHg = g_qhh + ((size_t)bh * Sq + qb * 128) * DP;
    const __half* kHg = g_khh + (size_t)bh * Sq * DP;
    const __half* kLg = g_khl + (size_t)bh * Sq * DP;
    const __half* vHg = g_vhh + (size_t)bh * Sq * DP;

    const int ldr = tid >> 3;           // 0..31 row base
    const int ldc = (tid & 7) * 8;      // fp16 col

#pragma unroll
    for (int i = 0; i < 4; i++) {
        int r = ldr + i * 32;
        uint32_t so = (uint32_t)(r * KLD + ldc) * 2;
        size_t gi = (size_t)r * DP + ldc;
        cp16(sb + OQH + so, qHg + gi);
        cp16(sb + OKV0 + SKH + so, kHg + gi);
        cp16(sb + OKV0 + SKL + so, kLg + gi);
        cp16(sb + OKV0 + SVH + so, vHg + gi);
    }
    CP_COMMIT();

    float accA[8][4];
#pragma unroll
    for (int j = 0; j < 8; j++)
#pragma unroll
        for (int x = 0; x < 4; x++) accA[j][x] = 0.0f;
    float rsum[2] = {0.f, 0.f};

    const int qrow0 = wid * 16;

    for (int kt = 0; kt < 16; kt++) {
        CP_WAIT0();
        __syncthreads();

        const uint32_t kvo = sb + OKV0 + (kt & 1) * KVBUF;

        if (kt < 15) {
            const uint32_t nxt = sb + OKV0 + ((kt + 1) & 1) * KVBUF;
            const size_t gbase = (size_t)(kt + 1) * 128 * DP;
#pragma unroll
            for (int i = 0; i < 4; i++) {
                int r = ldr + i * 32;
                uint32_t so = (uint32_t)(r * KLD + ldc) * 2;
                size_t gi = gbase + (size_t)r * DP + ldc;
                cp16(nxt + SKH + so, kHg + gi);
                cp16(nxt + SKL + so, kLg + gi);
                cp16(nxt + SVH + so, vHg + gi);
            }
            CP_COMMIT();
        }

        float s[16][4];
#pragma unroll
        for (int j = 0; j < 16; j++)
#pragma unroll
            for (int x = 0; x < 4; x++) s[j][x] = 0.0f;

        // ---- QK^T: qh*(kh + kl), plane-pass ordering ----
#pragma unroll
        for (int kk = 0; kk < 64; kk += 16) {
            uint32_t ah[4];
            uint32_t qoff = (uint32_t)((qrow0 + lrow) * KLD + kk + lcol) * 2;
            ldmat4(ah, sb + OQH + qoff);
            uint32_t bh4[8][4], bl4[8][4];
#pragma unroll
            for (int nt4 = 0; nt4 < 8; nt4++) {
                uint32_t koff = (uint32_t)((nt4 * 16 + lrow) * KLD + kk + lcol) * 2;
                ldmat4(bh4[nt4], kvo + SKH + koff);
                ldmat4(bl4[nt4], kvo + SKL + koff);
            }
#pragma unroll
            for (int nt4 = 0; nt4 < 8; nt4++) {
                mma16816h(s[2 * nt4],     ah, bh4[nt4][0], bh4[nt4][2]);
                mma16816h(s[2 * nt4 + 1], ah, bh4[nt4][1], bh4[nt4][3]);
            }
#pragma unroll
            for (int nt4 = 0; nt4 < 8; nt4++) {
                mma16816h(s[2 * nt4],     ah, bl4[nt4][0], bl4[nt4][2]);
                mma16816h(s[2 * nt4 + 1], ah, bl4[nt4][1], bl4[nt4][3]);
            }
        }

        // ---- epilogue: exp/mask -> wout; Eh fragments (fp16) ----
        uint32_t eh[8][4];
        const int ktbase = kt * 128;
#pragma unroll
        for (int j = 0; j < 16; j++) {
#pragma unroll
            for (int half = 0; half < 2; half++) {
                int ql = qrow0 + lrq + half * 8;
                size_t qg = (size_t)qb * 128 + ql;
                size_t gk = (size_t)ktbase + j * 8 + lc2;
                float2 mv = *(const float2*)&mask[((size_t)b * Sq + qg) * Sq + gk];
                float e0 = __expf(s[j][half * 2 + 0] * 0.125f + mv.x * (-1e9f));
                float e1 = __expf(s[j][half * 2 + 1] * 0.125f + mv.y * (-1e9f));
                *(float2*)&wout[((size_t)bh * Sq + qg) * Sq + gk] = make_float2(e0, e1);
                eh[j >> 1][(j & 1) * 2 + half] = pack2half(e0, e1);
                rsum[half] += e0 + e1;
            }
        }

        // ---- AV: Eh * Vh (1 plane) ----
#pragma unroll
        for (int kk8 = 0; kk8 < 8; kk8++) {
            uint32_t vh4[4][4];
#pragma unroll
            for (int dt4 = 0; dt4 < 4; dt4++) {
                uint32_t voff = (uint32_t)((kk8 * 16 + lrow) * KLD + dt4 * 16 + lcol) * 2;
                ldmat4t(vh4[dt4], kvo + SVH + voff);
            }
#pragma unroll
            for (int dt4 = 0; dt4 < 4; dt4++) {
                mma16816h(accA[dt4 * 2],     eh[kk8], vh4[dt4][0], vh4[dt4][1]);
                mma16816h(accA[dt4 * 2 + 1], eh[kk8], vh4[dt4][2], vh4[dt4][3]);
            }
        }
    }

#pragma unroll
    for (int half = 0; half < 2; half++) {
        float r = rsum[half];
        r += __shfl_xor_sync(0xFFFFFFFFu, r, 1);
        r += __shfl_xor_sync(0xFFFFFFFFu, r, 2);
        if ((lane & 3) == 0) RS[qrow0 + lrq + half * 8] = r;
    }
    __syncthreads();
    if (tid < 128) {
        float tot = RS[tid];
        g_rowsum[(size_t)bh * Sq + qb * 128 + tid] = tot;
        RS[tid] = 1.0f / tot;
    }
    __syncthreads();

#pragma unroll
    for (int nt = 0; nt < 8; nt++) {
        int dcol = nt * 8 + lc2;
#pragma unroll
        for (int half = 0; half < 2; half++) {
            int ql = qrow0 + lrq + half * 8;
            float inv = RS[ql];
            size_t qg = (size_t)qb * 128 + ql;
            float2 o = make_float2(accA[nt][half * 2] * inv,
                                   accA[nt][half * 2 + 1] * inv);
            *(float2*)&g_attn[((size_t)b * Sq + qg) * Dm + h * 64 + dcol] = o;
        }
    }
}

// ---------------------------------------------------------------------------
__global__ __launch_bounds__(128) void norm_kernel(float* __restrict__ w)
{
    int row = blockIdx.x;
    float inv = 1.0f / g_rowsum[row];
    float4* p = (float4*)(w + (size_t)row * Sq);
#pragma unroll
    for (int t = threadIdx.x; t < Sq / 4; t += 128) {
        float4 v = p[t];
        v.x *= inv; v.y *= inv; v.z *= inv; v.w *= inv;
        p[t] = v;
    }
}

// ---------------------------------------------------------------------------
extern "C" void kernel_launch(void* const* d_in, const int* in_sizes, int n_in,
                              void* d_out, int out_size)
{
    const float* q    = (const float*)d_in[0];
    const float* v    = (const float*)d_in[1];
    const float* k    = (const float*)d_in[2];
    const float* mask = (const float*)d_in[3];
    const float* wq_w = (const float*)d_in[4];
    const float* wq_b = (const float*)d_in[5];
    const float* wk_w = (const float*)d_in[6];
    const float* wk_b = (const float*)d_in[7];
    const float* wv_w = (const float*)d_in[8];
    const float* wv_b = (const float*)d_in[9];
    const float* dw   = (const float*)d_in[10];
    const float* db   = (const float*)d_in[11];

    float* out     = (float*)d_out;
    float* weights = out + (size_t)Mrows * Dm;

    __half *qhh, *qhl, *khh, *khl, *vhh, *vhl;
    float* attn;
    cudaGetSymbolAddress((void**)&qhh, g_qhh);
    cudaGetSymbolAddress((void**)&qhl, g_qhl);
    cudaGetSymbolAddress((void**)&khh, g_khh);
    cudaGetSymbolAddress((void**)&khl, g_khl);
    cudaGetSymbolAddress((void**)&vhh, g_vhh);
    cudaGetSymbolAddress((void**)&vhl, g_vhl);
    cudaGetSymbolAddress((void**)&attn, g_attn);

    dim3 g(Dm / 128, Mrows / 128);   // (8, 32)

    cudaFuncSetAttribute(attn_tc, cudaFuncAttributeMaxDynamicSharedMemorySize, ASMEM);

    // fork-join streams: run K/V projections and norm||dense concurrently
    cudaStream_t s2, s3;
    cudaStreamCreateWithFlags(&s2, cudaStreamNonBlocking);
    cudaStreamCreateWithFlags(&s3, cudaStreamNonBlocking);
    cudaEvent_t e0, ek, ev, e1, e2;
    cudaEventCreateWithFlags(&e0, cudaEventDisableTiming);
    cudaEventCreateWithFlags(&ek, cudaEventDisableTiming);
    cudaEventCreateWithFlags(&ev, cudaEventDisableTiming);
    cudaEventCreateWithFlags(&e1, cudaEventDisableTiming);
    cudaEventCreateWithFlags(&e2, cudaEventDisableTiming);

    cudaEventRecord(e0, 0);
    cudaStreamWaitEvent(s2, e0, 0);
    cudaStreamWaitEvent(s3, e0, 0);

    tc_gemm<<<g, 256, 0, 0>>>(q, wq_w, wq_b, nullptr, qhh, qhl, 1);
    tc_gemm<<<g, 256, 0, s2>>>(k, wk_w, wk_b, nullptr, khh, khl, 1);
    tc_gemm<<<g, 256, 0, s3>>>(v, wv_w, wv_b, nullptr, vhh, vhl, 1);

    cudaEventRecord(ek, s2);
    cudaEventRecord(ev, s3);
    cudaStreamWaitEvent(0, ek, 0);
    cudaStreamWaitEvent(0, ev, 0);

    attn_tc<<<dim3(Sq / 128, BH), 256, ASMEM, 0>>>(mask, weights);

    cudaEventRecord(e1, 0);
    cudaStreamWaitEvent(s2, e1, 0);
    norm_kernel<<<BH * Sq, 128, 0, s2>>>(weights);
    cudaEventRecord(e2, s2);

    tc_gemm<<<g, 256, 0, 0>>>(attn, dw, db, out, nullptr, nullptr, 0);

    cudaStreamWaitEvent(0, e2, 0);

    cudaEventDestroy(e0);
    cudaEventDestroy(ek);
    cudaEventDestroy(ev);
    cudaEventDestroy(e1);
    cudaEventDestroy(e2);
    cudaStreamDestroy(s2);
    cudaStreamDestroy(s3);
}